// round 11
// baseline (speedup 1.0000x reference)
#include <cuda_runtime.h>
#include <cuda_fp16.h>

#define NROWS 8192
#define HW    4096

__device__ __half g_wq [64  * 4096];
__device__ __half g_wk [64  * 4096];
__device__ __half g_wv [128 * 4096];   // cols 0..49: w_v; 64..113: w_fc rows
__device__ __half g_wfc[4096 * 64];
__device__ float  g_Pq [NROWS * 64];
__device__ float  g_Pk [NROWS * 64];
__device__ float  g_Pv [NROWS * 64];
__device__ float  g_Rv [NROWS * 64];
__device__ float  g_rs [NROWS];
__device__ float  g_rss[NROWS];
__device__ float  g_colsum[64];
__device__ float  g_G  [2500];
__device__ float  g_lp [32 * 8 * 25];
__device__ float  g_attn[32 * 25];
__device__ __half g_Va [NROWS * 64];
__device__ float  g_part[NROWS * 2];
__device__ float  g_sc[256];
__device__ float  g_sh[256];

__device__ __forceinline__ void mma16816(float* c, const unsigned* a,
                                         unsigned b0, unsigned b1) {
    asm volatile(
        "mma.sync.aligned.m16n8k16.row.col.f32.f16.f16.f32 "
        "{%0,%1,%2,%3}, {%4,%5,%6,%7}, {%8,%9}, {%0,%1,%2,%3};\n"
        : "+f"(c[0]), "+f"(c[1]), "+f"(c[2]), "+f"(c[3])
        : "r"(a[0]), "r"(a[1]), "r"(a[2]), "r"(a[3]), "r"(b0), "r"(b1));
}

// ---- K0a: weight transpose/convert/pad ----
__global__ void k_prep(const float* __restrict__ wq, const float* __restrict__ wk,
                       const float* __restrict__ wv, const float* __restrict__ wfc) {
    int i0 = blockIdx.x * 256 + threadIdx.x, stride = gridDim.x * 256;
    for (int idx = i0; idx < 64 * 4096; idx += stride) {
        int n = idx >> 12, kk = idx & 4095;
        g_wq[idx] = __float2half(n < 50 ? wq[kk * 50 + n] : 0.f);
        g_wk[idx] = __float2half(n < 50 ? wk[kk * 50 + n] : 0.f);
    }
    for (int idx = i0; idx < 128 * 4096; idx += stride) {
        int n = idx >> 12, kk = idx & 4095;
        float val = 0.f;
        if (n < 50) val = wv[kk * 50 + n];
        else if (n >= 64 && n < 114) val = wfc[(n - 64) * 4096 + kk];
        g_wv[idx] = __float2half(val);
    }
    for (int idx = i0; idx < 4096 * 64; idx += stride) {
        int p = idx >> 6, j = idx & 63;
        g_wfc[idx] = __float2half(j < 50 ? wfc[j * 4096 + p] : 0.f);
    }
}

// ---- K0b: colsum(w_fc) ----
__global__ void k_colsum(const float* __restrict__ wfc) {
    __shared__ float red[128];
    int bid = blockIdx.x, t = threadIdx.x;
    const float* r = wfc + bid * 4096;
    float acc = 0.f;
    for (int p = t; p < 4096; p += 128) acc += r[p];
    red[t] = acc; __syncthreads();
    for (int s = 64; s > 0; s >>= 1) { if (t < s) red[t] += red[t + s]; __syncthreads(); }
    if (t == 0) g_colsum[bid] = red[0];
}

// ---- K0c: G = w_fc w_fc^T ----
__global__ void k_gram(const float* __restrict__ wfc) {
    __shared__ float red[128];
    int pair = blockIdx.x, t = threadIdx.x;
    const float* ri = wfc + (pair / 50) * 4096;
    const float* rj = wfc + (pair % 50) * 4096;
    float acc = 0.f;
    for (int p = t; p < 4096; p += 128) acc += ri[p] * rj[p];
    red[t] = acc; __syncthreads();
    for (int s = 64; s > 0; s >>= 1) { if (t < s) red[t] += red[t + s]; __syncthreads(); }
    if (t == 0) g_G[pair] = red[0];
}

// ---- K1: projections (fp16 mma, 4-stage smem pipeline, fused row sums) ----
template <int NB, bool SUMS>
__device__ __forceinline__ void proj_body(const float* __restrict__ A,
                                          const __half* __restrict__ W,
                                          float* __restrict__ OutL, int rowbase,
                                          __half (*As)[128][40], __half (*Bs)[128][40]) {
    const int NT = NB / 16;
    int t = threadIdx.x, warp = t >> 5, lane = t & 31;
    int g = lane >> 2, tig = lane & 3;
    int warpM = warp >> 1, warpN = warp & 1;
    int a_r = t >> 3, a_c = (t & 7) * 4;
    int b_n = t >> 4, b_k = (t & 15) * 2;
    const float* Aptr = A + (long)rowbase * HW;

    float rs_p[4] = {0,0,0,0}, rss_p[4] = {0,0,0,0};
    float acc[2][NT][4];
#pragma unroll
    for (int i = 0; i < 2; i++)
#pragma unroll
        for (int j = 0; j < NT; j++)
#pragma unroll
            for (int l = 0; l < 4; l++) acc[i][j][l] = 0.f;

    float4 aregs[4];
    unsigned bregs[NT];

    auto loadRegs = [&](int ch) {
        int k0 = ch * 32;
#pragma unroll
        for (int p = 0; p < 4; p++)
            aregs[p] = *reinterpret_cast<const float4*>(Aptr + (long)(p * 32 + a_r) * HW + k0 + a_c);
#pragma unroll
        for (int p = 0; p < NT; p++)
            bregs[p] = *reinterpret_cast<const unsigned*>(W + (long)(p * 16 + b_n) * HW + k0 + b_k);
    };
    auto storeRegs = [&](int buf) {
#pragma unroll
        for (int p = 0; p < 4; p++) {
            float4 x = aregs[p];
            if (SUMS) {
                rs_p[p]  += x.x + x.y + x.z + x.w;
                rss_p[p] += x.x*x.x + x.y*x.y + x.z*x.z + x.w*x.w;
            }
            *reinterpret_cast<__half2*>(&As[buf][p*32+a_r][a_c])   = __floats2half2_rn(x.x, x.y);
            *reinterpret_cast<__half2*>(&As[buf][p*32+a_r][a_c+2]) = __floats2half2_rn(x.z, x.w);
        }
#pragma unroll
        for (int p = 0; p < NT; p++)
            *reinterpret_cast<unsigned*>(&Bs[buf][p*16+b_n][b_k]) = bregs[p];
    };
    auto mmastep = [&](int buf) {
#pragma unroll
        for (int ks = 0; ks < 32; ks += 16) {
            unsigned a[2][4];
#pragma unroll
            for (int mt = 0; mt < 2; mt++) {
                int r0 = warpM*32 + mt*16 + g;
                a[mt][0] = *reinterpret_cast<unsigned*>(&As[buf][r0]  [ks+tig*2]);
                a[mt][1] = *reinterpret_cast<unsigned*>(&As[buf][r0+8][ks+tig*2]);
                a[mt][2] = *reinterpret_cast<unsigned*>(&As[buf][r0]  [ks+tig*2+8]);
                a[mt][3] = *reinterpret_cast<unsigned*>(&As[buf][r0+8][ks+tig*2+8]);
            }
#pragma unroll
            for (int nt = 0; nt < NT; nt++) {
                int n0 = warpN*(NB/2) + nt*8 + g;
                unsigned b0 = *reinterpret_cast<unsigned*>(&Bs[buf][n0][ks+tig*2]);
                unsigned b1 = *reinterpret_cast<unsigned*>(&Bs[buf][n0][ks+tig*2+8]);
                mma16816(acc[0][nt], a[0], b0, b1);
                mma16816(acc[1][nt], a[1], b0, b1);
            }
        }
    };

    // 4-stage pipeline, barrier every 2 chunks
    loadRegs(0); storeRegs(0);
    loadRegs(1); storeRegs(1);
    __syncthreads();
#pragma unroll 1
    for (int ch = 0; ch < 128; ch += 2) {
        bool m2 = ch + 2 < 128, m3 = ch + 3 < 128;
        if (m2) loadRegs(ch + 2);
        mmastep(ch & 3);
        if (m2) storeRegs((ch + 2) & 3);
        if (m3) loadRegs(ch + 3);
        mmastep((ch + 1) & 3);
        if (m3) storeRegs((ch + 3) & 3);
        if (m2) __syncthreads();
    }

#pragma unroll
    for (int mt = 0; mt < 2; mt++)
#pragma unroll
        for (int nt = 0; nt < NT; nt++) {
            int r0 = rowbase + warpM*32 + mt*16 + g;
            int cc = warpN*(NB/2) + nt*8 + tig*2;
            float* dst; int c2;
            if (NB == 64 || cc < 64) { dst = OutL; c2 = cc; }
            else                     { dst = g_Rv; c2 = cc - 64; }
            dst[(long)r0*64 + c2]       = acc[mt][nt][0];
            dst[(long)r0*64 + c2 + 1]   = acc[mt][nt][1];
            dst[(long)(r0+8)*64 + c2]   = acc[mt][nt][2];
            dst[(long)(r0+8)*64 + c2+1] = acc[mt][nt][3];
        }
    if (SUMS) {
#pragma unroll
        for (int p = 0; p < 4; p++) {
            float s = rs_p[p], ss = rss_p[p];
            s  += __shfl_xor_sync(0xffffffffu, s, 1);
            s  += __shfl_xor_sync(0xffffffffu, s, 2);
            s  += __shfl_xor_sync(0xffffffffu, s, 4);
            ss += __shfl_xor_sync(0xffffffffu, ss, 1);
            ss += __shfl_xor_sync(0xffffffffu, ss, 2);
            ss += __shfl_xor_sync(0xffffffffu, ss, 4);
            if ((lane & 7) == 0) {
                int row = rowbase + p*32 + a_r;
                g_rs[row] = s; g_rss[row] = ss;
            }
        }
    }
}

// Heavy fused-v blocks first (bid 0..63) so the 2x-work CTAs all start in wave 1.
__global__ __launch_bounds__(256) void k_proj(const float* __restrict__ q,
                                              const float* __restrict__ k,
                                              const float* __restrict__ v) {
    extern __shared__ __half sh[];
    __half (*As)[128][40] = reinterpret_cast<__half(*)[128][40]>(sh);
    __half (*Bs)[128][40] = reinterpret_cast<__half(*)[128][40]>(sh + 4 * 128 * 40);
    int bid = blockIdx.x;
    if (bid < 64)       proj_body<128, true >(v, g_wv, g_Pv, bid * 128, As, Bs);
    else if (bid < 128) proj_body<64,  false>(q, g_wq, g_Pq, (bid - 64) * 128, As, Bs);
    else                proj_body<64,  false>(k, g_wk, g_Pk, (bid - 128) * 128, As, Bs);
}

// ---- K2a: partial logits, grid (8, 32) ----
__global__ __launch_bounds__(256) void k_logits() {
    __shared__ float sred[8][25];
    int b = blockIdx.y, s = blockIdx.x, t = threadIdx.x;
    int warp = t >> 5, lane = t & 31;

    float lp[25];
#pragma unroll
    for (int i = 0; i < 25; i++) lp[i] = 0.f;
    for (int i = t; i < 320; i += 256) {
        int f = s * 320 + i;
        int c = f / 10, l = f - c * 10;
        long base = ((long)b * 256 + c) * 64;
        float qv[5], kv[5];
#pragma unroll
        for (int x = 0; x < 5; x++) { qv[x] = g_Pq[base + x*10 + l]; kv[x] = g_Pk[base + x*10 + l]; }
#pragma unroll
        for (int x = 0; x < 5; x++)
#pragma unroll
            for (int j = 0; j < 5; j++) lp[x*5+j] += qv[x] * kv[j];
    }
#pragma unroll
    for (int x = 0; x < 25; x++) {
        float r = lp[x];
        for (int o = 16; o > 0; o >>= 1) r += __shfl_xor_sync(0xffffffffu, r, o);
        if (lane == 0) sred[warp][x] = r;
    }
    __syncthreads();
    if (t < 25) {
        float r = 0.f;
        for (int w = 0; w < 8; w++) r += sred[w][t];
        g_lp[(b * 8 + s) * 25 + t] = r;
    }
}

// ---- K2b: reduce partials + softmax ----
__global__ void k_softfin() {
    __shared__ float sl[25];
    int b = blockIdx.x, t = threadIdx.x;   // 32 threads
    if (t < 25) {
        float s = 0.f;
        for (int p = 0; p < 8; p++) s += g_lp[(b * 8 + p) * 25 + t];
        sl[t] = s * (1.0f / 50.596442562694074f);  // 1/sqrt(2560)
    }
    __syncwarp();
    if (t < 5) {
        float m = -1e30f;
        for (int j = 0; j < 5; j++) m = fmaxf(m, sl[t*5+j]);
        float e[5], se = 0.f;
        for (int j = 0; j < 5; j++) { e[j] = expf(sl[t*5+j] - m); se += e[j]; }
        float inv = 1.0f / se;
        for (int j = 0; j < 5; j++) g_attn[b*25 + t*5+j] = e[j] * inv;
    }
}

// ---- K2c: row-parallel Va mixing + BN partials. One warp per row. ----
__global__ __launch_bounds__(256) void k_mix() {
    __shared__ float sG[2500];
    __shared__ float scs[50];
    __shared__ float sattn[25];
    __shared__ float spv[8][64];
    __shared__ float sva[8][64];
    int t = threadIdx.x, w = t >> 5, lane = t & 31;
    long row0 = (long)blockIdx.x * 8;
    int b = (int)(row0 >> 8);

    for (int i = t; i < 2500; i += 256) sG[i] = g_G[i];
    if (t < 50) scs[t] = g_colsum[t];
    if (t < 25) sattn[t] = g_attn[b*25 + t];
    long row = row0 + w;
    spv[w][lane]      = g_Pv[row*64 + lane];
    spv[w][lane + 32] = g_Pv[row*64 + lane + 32];
    __syncthreads();

    for (int c = lane; c < 50; c += 32) {
        int i = c / 10, l = c - 10 * i;
        float s = spv[w][c];
#pragma unroll
        for (int j = 0; j < 5; j++) s += sattn[i*5 + j] * spv[w][j*10 + l];
        float h = __half2float(__float2half(s));
        sva[w][c] = h;
        g_Va[row*64 + c] = __float2half(h);
    }
    for (int c = 50 + lane; c < 64; c += 32) g_Va[row*64 + c] = __float2half(0.f);
    __syncwarp();

    float s1 = 0.f, s2 = 0.f;
    for (int c = lane; c < 50; c += 32) {
        float vac = sva[w][c];
        s1 += vac * scs[c];
        s2 += 2.f * vac * g_Rv[row*64 + c];
        float tt = 0.f;
        for (int j2 = 0; j2 < 50; j2++) tt += sG[c*50 + j2] * sva[w][j2];
        s2 += vac * tt;
    }
#pragma unroll
    for (int o = 16; o > 0; o >>= 1) {
        s1 += __shfl_xor_sync(0xffffffffu, s1, o);
        s2 += __shfl_xor_sync(0xffffffffu, s2, o);
    }
    if (lane == 0) {
        g_part[row*2]     = g_rs[row]  + s1;
        g_part[row*2 + 1] = g_rss[row] + s2;
    }
}

// ---- K2d: per-channel BN scale/shift ----
__global__ void k_stats(const float* __restrict__ gamma, const float* __restrict__ beta) {
    int c = threadIdx.x;
    float s1 = 0.f, s2 = 0.f;
    for (int b = 0; b < 32; b++) {
        long r = ((long)b * 256 + c) * 2;
        s1 += g_part[r]; s2 += g_part[r + 1];
    }
    const float invN = 1.0f / 131072.0f;
    float mean = s1 * invN;
    float var  = s2 * invN - mean * mean;
    float sc   = gamma[c] * rsqrtf(var + 1e-5f);
    g_sc[c] = sc;
    g_sh[c] = beta[c] - mean * sc;
}

// ---- K3: out = (vf + Va @ w_fc) * sc + sh ----
__global__ __launch_bounds__(256) void k_final(const float* __restrict__ v,
                                               float* __restrict__ out) {
    __shared__ __half As[128][72];
    __shared__ __half Bs[128][72];
    __shared__ float sSc[128], sSh[128];
    int rb = blockIdx.x * 128, cb = blockIdx.y * 128;
    int t = threadIdx.x, warp = t >> 5, lane = t & 31;
    int g = lane >> 2, tig = lane & 3;
    int warpM = warp >> 1, warpN = warp & 1;

    for (int i = t; i < 2048; i += 256) {
        int r = i >> 4, s = i & 15;
        *reinterpret_cast<uint2*>(&As[r][s*4]) =
            *reinterpret_cast<const uint2*>(&g_Va[(long)(rb + r)*64 + s*4]);
    }
    for (int i = t; i < 2048; i += 256) {
        int p = i >> 4, s = i & 15;
        *reinterpret_cast<uint2*>(&Bs[p][s*4]) =
            *reinterpret_cast<const uint2*>(&g_wfc[(long)(cb + p)*64 + s*4]);
    }
    if (t < 128) { int ch = (rb + t) & 255; sSc[t] = g_sc[ch]; sSh[t] = g_sh[ch]; }
    __syncthreads();

    float acc[2][8][4];
#pragma unroll
    for (int i = 0; i < 2; i++)
#pragma unroll
        for (int j = 0; j < 8; j++)
#pragma unroll
            for (int l = 0; l < 4; l++) acc[i][j][l] = 0.f;

#pragma unroll
    for (int ks = 0; ks < 64; ks += 16) {
        unsigned a[2][4];
#pragma unroll
        for (int mt = 0; mt < 2; mt++) {
            int r0 = warpM*32 + mt*16 + g;
            a[mt][0] = *reinterpret_cast<unsigned*>(&As[r0]  [ks+tig*2]);
            a[mt][1] = *reinterpret_cast<unsigned*>(&As[r0+8][ks+tig*2]);
            a[mt][2] = *reinterpret_cast<unsigned*>(&As[r0]  [ks+tig*2+8]);
            a[mt][3] = *reinterpret_cast<unsigned*>(&As[r0+8][ks+tig*2+8]);
        }
#pragma unroll
        for (int nt = 0; nt < 8; nt++) {
            int n0 = warpN*64 + nt*8 + g;
            unsigned b0 = *reinterpret_cast<unsigned*>(&Bs[n0][ks+tig*2]);
            unsigned b1 = *reinterpret_cast<unsigned*>(&Bs[n0][ks+tig*2+8]);
            mma16816(acc[0][nt], a[0], b0, b1);
            mma16816(acc[1][nt], a[1], b0, b1);
        }
    }

#pragma unroll
    for (int mt = 0; mt < 2; mt++) {
        int lr = warpM*32 + mt*16 + g;
        float sc0 = sSc[lr],   sh0 = sSh[lr];
        float sc1 = sSc[lr+8], sh1 = sSh[lr+8];
        long r0 = rb + lr;
#pragma unroll
        for (int nt = 0; nt < 8; nt++) {
            long col = cb + warpN*64 + nt*8 + tig*2;
            float2 v0 = *reinterpret_cast<const float2*>(v + r0*HW + col);
            float2 v1 = *reinterpret_cast<const float2*>(v + (r0+8)*HW + col);
            float2 o0, o1;
            o0.x = (v0.x + acc[mt][nt][0]) * sc0 + sh0;
            o0.y = (v0.y + acc[mt][nt][1]) * sc0 + sh0;
            o1.x = (v1.x + acc[mt][nt][2]) * sc1 + sh1;
            o1.y = (v1.y + acc[mt][nt][3]) * sc1 + sh1;
            *reinterpret_cast<float2*>(out + r0*HW + col)     = o0;
            *reinterpret_cast<float2*>(out + (r0+8)*HW + col) = o1;
        }
    }
}

extern "C" void kernel_launch(void* const* d_in, const int* in_sizes, int n_in,
                              void* d_out, int out_size) {
    const float* q     = (const float*)d_in[0];
    const float* k     = (const float*)d_in[1];
    const float* v     = (const float*)d_in[2];
    const float* wq    = (const float*)d_in[3];
    const float* wk    = (const float*)d_in[4];
    const float* wv    = (const float*)d_in[5];
    const float* wfc   = (const float*)d_in[6];
    const float* gamma = (const float*)d_in[7];
    const float* beta  = (const float*)d_in[8];
    float* out = (float*)d_out;

    static int smem_set = 0;
    if (!smem_set) {
        cudaFuncSetAttribute(k_proj, cudaFuncAttributeMaxDynamicSharedMemorySize, 81920);
        smem_set = 1;
    }

    k_prep<<<1024, 256>>>(wq, wk, wv, wfc);
    k_colsum<<<50, 128>>>(wfc);
    k_gram<<<2500, 128>>>(wfc);
    k_proj<<<192, 256, 81920>>>(q, k, v);       // profiled slot (launch index 3)
    k_logits<<<dim3(8, 32), 256>>>();
    k_softfin<<<32, 32>>>();
    k_mix<<<1024, 256>>>();
    k_stats<<<1, 256>>>(gamma, beta);
    k_final<<<dim3(64, 32), 256>>>(v, out);
}

// round 13
// speedup vs baseline: 1.0264x; 1.0264x over previous
#include <cuda_runtime.h>
#include <cuda_fp16.h>

#define NROWS 8192
#define HW    4096
#define HALF_K 2048

__device__ __half g_wq [64  * 4096];
__device__ __half g_wk [64  * 4096];
__device__ __half g_wv [128 * 4096];   // cols 0..49: w_v; 64..113: w_fc rows
__device__ __half g_wfc[4096 * 64];
__device__ float  g_Pq [2 * NROWS * 64];   // [split][row][64]
__device__ float  g_Pk [2 * NROWS * 64];
__device__ float  g_Pv [2 * NROWS * 64];
__device__ float  g_Rv [2 * NROWS * 64];
__device__ float  g_rs [2 * NROWS];
__device__ float  g_rss[2 * NROWS];
__device__ float  g_colsum[64];
__device__ float  g_G  [2500];
__device__ float  g_lp [32 * 8 * 25];
__device__ float  g_attn[32 * 25];
__device__ __half g_Va [NROWS * 64];
__device__ float  g_part[NROWS * 2];
__device__ float  g_sc[256];
__device__ float  g_sh[256];

__device__ __forceinline__ void mma16816(float* c, const unsigned* a,
                                         unsigned b0, unsigned b1) {
    asm volatile(
        "mma.sync.aligned.m16n8k16.row.col.f32.f16.f16.f32 "
        "{%0,%1,%2,%3}, {%4,%5,%6,%7}, {%8,%9}, {%0,%1,%2,%3};\n"
        : "+f"(c[0]), "+f"(c[1]), "+f"(c[2]), "+f"(c[3])
        : "r"(a[0]), "r"(a[1]), "r"(a[2]), "r"(a[3]), "r"(b0), "r"(b1));
}

// ---- K0a: weight transpose/convert/pad ----
__global__ void k_prep(const float* __restrict__ wq, const float* __restrict__ wk,
                       const float* __restrict__ wv, const float* __restrict__ wfc) {
    int i0 = blockIdx.x * 256 + threadIdx.x, stride = gridDim.x * 256;
    for (int idx = i0; idx < 64 * 4096; idx += stride) {
        int n = idx >> 12, kk = idx & 4095;
        g_wq[idx] = __float2half(n < 50 ? wq[kk * 50 + n] : 0.f);
        g_wk[idx] = __float2half(n < 50 ? wk[kk * 50 + n] : 0.f);
    }
    for (int idx = i0; idx < 128 * 4096; idx += stride) {
        int n = idx >> 12, kk = idx & 4095;
        float val = 0.f;
        if (n < 50) val = wv[kk * 50 + n];
        else if (n >= 64 && n < 114) val = wfc[(n - 64) * 4096 + kk];
        g_wv[idx] = __float2half(val);
    }
    for (int idx = i0; idx < 4096 * 64; idx += stride) {
        int p = idx >> 6, j = idx & 63;
        g_wfc[idx] = __float2half(j < 50 ? wfc[j * 4096 + p] : 0.f);
    }
}

// ---- K0b: colsum(w_fc) ----
__global__ void k_colsum(const float* __restrict__ wfc) {
    __shared__ float red[128];
    int bid = blockIdx.x, t = threadIdx.x;
    const float* r = wfc + bid * 4096;
    float acc = 0.f;
    for (int p = t; p < 4096; p += 128) acc += r[p];
    red[t] = acc; __syncthreads();
    for (int s = 64; s > 0; s >>= 1) { if (t < s) red[t] += red[t + s]; __syncthreads(); }
    if (t == 0) g_colsum[bid] = red[0];
}

// ---- K0c: G = w_fc w_fc^T ----
__global__ void k_gram(const float* __restrict__ wfc) {
    __shared__ float red[128];
    int pair = blockIdx.x, t = threadIdx.x;
    const float* ri = wfc + (pair / 50) * 4096;
    const float* rj = wfc + (pair % 50) * 4096;
    float acc = 0.f;
    for (int p = t; p < 4096; p += 128) acc += ri[p] * rj[p];
    red[t] = acc; __syncthreads();
    for (int s = 64; s > 0; s >>= 1) { if (t < s) red[t] += red[t + s]; __syncthreads(); }
    if (t == 0) g_G[pair] = red[0];
}

// ---- K1: projections, split-K x2 (fp16 mma, 4-stage pipeline, fused row sums) ----
template <int NB, bool SUMS>
__device__ __forceinline__ void proj_body(const float* __restrict__ A,
                                          const __half* __restrict__ W,
                                          float* __restrict__ OutL,
                                          float* __restrict__ RvL,
                                          float* __restrict__ rsL,
                                          float* __restrict__ rssL,
                                          int rowbase, int kbase,
                                          __half (*As)[128][40], __half (*Bs)[128][40]) {
    const int NT = NB / 16;
    const int NCH = HALF_K / 32;   // 64 chunks
    int t = threadIdx.x, warp = t >> 5, lane = t & 31;
    int g = lane >> 2, tig = lane & 3;
    int warpM = warp >> 1, warpN = warp & 1;
    int a_r = t >> 3, a_c = (t & 7) * 4;
    int b_n = t >> 4, b_k = (t & 15) * 2;
    const float* Aptr = A + (long)rowbase * HW + kbase;
    const __half* Wptr = W + kbase;

    float rs_p[4] = {0,0,0,0}, rss_p[4] = {0,0,0,0};
    float acc[2][NT][4];
#pragma unroll
    for (int i = 0; i < 2; i++)
#pragma unroll
        for (int j = 0; j < NT; j++)
#pragma unroll
            for (int l = 0; l < 4; l++) acc[i][j][l] = 0.f;

    float4 aregs[4];
    unsigned bregs[NT];

    auto loadRegs = [&](int ch) {
        int k0 = ch * 32;
#pragma unroll
        for (int p = 0; p < 4; p++)
            aregs[p] = *reinterpret_cast<const float4*>(Aptr + (long)(p * 32 + a_r) * HW + k0 + a_c);
#pragma unroll
        for (int p = 0; p < NT; p++)
            bregs[p] = *reinterpret_cast<const unsigned*>(Wptr + (long)(p * 16 + b_n) * HW + k0 + b_k);
    };
    auto storeRegs = [&](int buf) {
#pragma unroll
        for (int p = 0; p < 4; p++) {
            float4 x = aregs[p];
            if (SUMS) {
                rs_p[p]  += x.x + x.y + x.z + x.w;
                rss_p[p] += x.x*x.x + x.y*x.y + x.z*x.z + x.w*x.w;
            }
            *reinterpret_cast<__half2*>(&As[buf][p*32+a_r][a_c])   = __floats2half2_rn(x.x, x.y);
            *reinterpret_cast<__half2*>(&As[buf][p*32+a_r][a_c+2]) = __floats2half2_rn(x.z, x.w);
        }
#pragma unroll
        for (int p = 0; p < NT; p++)
            *reinterpret_cast<unsigned*>(&Bs[buf][p*16+b_n][b_k]) = bregs[p];
    };
    auto mmastep = [&](int buf) {
#pragma unroll
        for (int ks = 0; ks < 32; ks += 16) {
            unsigned a[2][4];
#pragma unroll
            for (int mt = 0; mt < 2; mt++) {
                int r0 = warpM*32 + mt*16 + g;
                a[mt][0] = *reinterpret_cast<unsigned*>(&As[buf][r0]  [ks+tig*2]);
                a[mt][1] = *reinterpret_cast<unsigned*>(&As[buf][r0+8][ks+tig*2]);
                a[mt][2] = *reinterpret_cast<unsigned*>(&As[buf][r0]  [ks+tig*2+8]);
                a[mt][3] = *reinterpret_cast<unsigned*>(&As[buf][r0+8][ks+tig*2+8]);
            }
#pragma unroll
            for (int nt = 0; nt < NT; nt++) {
                int n0 = warpN*(NB/2) + nt*8 + g;
                unsigned b0 = *reinterpret_cast<unsigned*>(&Bs[buf][n0][ks+tig*2]);
                unsigned b1 = *reinterpret_cast<unsigned*>(&Bs[buf][n0][ks+tig*2+8]);
                mma16816(acc[0][nt], a[0], b0, b1);
                mma16816(acc[1][nt], a[1], b0, b1);
            }
        }
    };

    // 4-stage pipeline, barrier every 2 chunks
    loadRegs(0); storeRegs(0);
    loadRegs(1); storeRegs(1);
    __syncthreads();
#pragma unroll 1
    for (int ch = 0; ch < NCH; ch += 2) {
        bool m2 = ch + 2 < NCH, m3 = ch + 3 < NCH;
        if (m2) loadRegs(ch + 2);
        mmastep(ch & 3);
        if (m2) storeRegs((ch + 2) & 3);
        if (m3) loadRegs(ch + 3);
        mmastep((ch + 1) & 3);
        if (m3) storeRegs((ch + 3) & 3);
        if (m2) __syncthreads();
    }

#pragma unroll
    for (int mt = 0; mt < 2; mt++)
#pragma unroll
        for (int nt = 0; nt < NT; nt++) {
            int r0 = rowbase + warpM*32 + mt*16 + g;
            int cc = warpN*(NB/2) + nt*8 + tig*2;
            float* dst; int c2;
            if (NB == 64 || cc < 64) { dst = OutL; c2 = cc; }
            else                     { dst = RvL; c2 = cc - 64; }
            dst[(long)r0*64 + c2]       = acc[mt][nt][0];
            dst[(long)r0*64 + c2 + 1]   = acc[mt][nt][1];
            dst[(long)(r0+8)*64 + c2]   = acc[mt][nt][2];
            dst[(long)(r0+8)*64 + c2+1] = acc[mt][nt][3];
        }
    if (SUMS) {
#pragma unroll
        for (int p = 0; p < 4; p++) {
            float s = rs_p[p], ss = rss_p[p];
            s  += __shfl_xor_sync(0xffffffffu, s, 1);
            s  += __shfl_xor_sync(0xffffffffu, s, 2);
            s  += __shfl_xor_sync(0xffffffffu, s, 4);
            ss += __shfl_xor_sync(0xffffffffu, ss, 1);
            ss += __shfl_xor_sync(0xffffffffu, ss, 2);
            ss += __shfl_xor_sync(0xffffffffu, ss, 4);
            if ((lane & 7) == 0) {
                int row = rowbase + p*32 + a_r;
                rsL[row] = s; rssL[row] = ss;
            }
        }
    }
}

// 384 CTAs: bid 0..127 = v (tile, split), 128..255 = q, 256..383 = k.
// Heavy fused-v blocks first so all 2x-work CTAs start in wave 1.
__global__ __launch_bounds__(256) void k_proj(const float* __restrict__ q,
                                              const float* __restrict__ k,
                                              const float* __restrict__ v) {
    extern __shared__ __half sh[];
    __half (*As)[128][40] = reinterpret_cast<__half(*)[128][40]>(sh);
    __half (*Bs)[128][40] = reinterpret_cast<__half(*)[128][40]>(sh + 4 * 128 * 40);
    int bid = blockIdx.x;
    if (bid < 128) {
        int split = bid & 1, tile = bid >> 1;
        long off = (long)split * NROWS * 64;
        proj_body<128, true >(v, g_wv, g_Pv + off, g_Rv + off,
                              g_rs + split * NROWS, g_rss + split * NROWS,
                              tile * 128, split * HALF_K, As, Bs);
    } else if (bid < 256) {
        int split = bid & 1, tile = (bid - 128) >> 1;
        proj_body<64, false>(q, g_wq, g_Pq + (long)split * NROWS * 64, nullptr,
                             nullptr, nullptr, tile * 128, split * HALF_K, As, Bs);
    } else {
        int split = bid & 1, tile = (bid - 256) >> 1;
        proj_body<64, false>(k, g_wk, g_Pk + (long)split * NROWS * 64, nullptr,
                             nullptr, nullptr, tile * 128, split * HALF_K, As, Bs);
    }
}

// ---- K2a: partial logits, grid (8, 32); sums the two K-split halves ----
__global__ __launch_bounds__(256) void k_logits() {
    __shared__ float sred[8][25];
    int b = blockIdx.y, s = blockIdx.x, t = threadIdx.x;
    int warp = t >> 5, lane = t & 31;
    const long H = (long)NROWS * 64;

    float lp[25];
#pragma unroll
    for (int i = 0; i < 25; i++) lp[i] = 0.f;
    for (int i = t; i < 320; i += 256) {
        int f = s * 320 + i;
        int c = f / 10, l = f - c * 10;
        long base = ((long)b * 256 + c) * 64;
        float qv[5], kv[5];
#pragma unroll
        for (int x = 0; x < 5; x++) {
            qv[x] = g_Pq[base + x*10 + l] + g_Pq[H + base + x*10 + l];
            kv[x] = g_Pk[base + x*10 + l] + g_Pk[H + base + x*10 + l];
        }
#pragma unroll
        for (int x = 0; x < 5; x++)
#pragma unroll
            for (int j = 0; j < 5; j++) lp[x*5+j] += qv[x] * kv[j];
    }
#pragma unroll
    for (int x = 0; x < 25; x++) {
        float r = lp[x];
        for (int o = 16; o > 0; o >>= 1) r += __shfl_xor_sync(0xffffffffu, r, o);
        if (lane == 0) sred[warp][x] = r;
    }
    __syncthreads();
    if (t < 25) {
        float r = 0.f;
        for (int w = 0; w < 8; w++) r += sred[w][t];
        g_lp[(b * 8 + s) * 25 + t] = r;
    }
}

// ---- K2b: reduce partials + softmax ----
__global__ void k_softfin() {
    __shared__ float sl[25];
    int b = blockIdx.x, t = threadIdx.x;   // 32 threads
    if (t < 25) {
        float s = 0.f;
        for (int p = 0; p < 8; p++) s += g_lp[(b * 8 + p) * 25 + t];
        sl[t] = s * (1.0f / 50.596442562694074f);  // 1/sqrt(2560)
    }
    __syncwarp();
    if (t < 5) {
        float m = -1e30f;
        for (int j = 0; j < 5; j++) m = fmaxf(m, sl[t*5+j]);
        float e[5], se = 0.f;
        for (int j = 0; j < 5; j++) { e[j] = expf(sl[t*5+j] - m); se += e[j]; }
        float inv = 1.0f / se;
        for (int j = 0; j < 5; j++) g_attn[b*25 + t*5+j] = e[j] * inv;
    }
}

// ---- K2c: row-parallel Va mixing + BN partials; sums K-split halves ----
__global__ __launch_bounds__(256) void k_mix() {
    __shared__ float sG[2500];
    __shared__ float scs[50];
    __shared__ float sattn[25];
    __shared__ float spv[8][64];
    __shared__ float sva[8][64];
    int t = threadIdx.x, w = t >> 5, lane = t & 31;
    long row0 = (long)blockIdx.x * 8;
    int b = (int)(row0 >> 8);
    const long H = (long)NROWS * 64;

    for (int i = t; i < 2500; i += 256) sG[i] = g_G[i];
    if (t < 50) scs[t] = g_colsum[t];
    if (t < 25) sattn[t] = g_attn[b*25 + t];
    long row = row0 + w;
    spv[w][lane]      = g_Pv[row*64 + lane]      + g_Pv[H + row*64 + lane];
    spv[w][lane + 32] = g_Pv[row*64 + lane + 32] + g_Pv[H + row*64 + lane + 32];
    __syncthreads();

    for (int c = lane; c < 50; c += 32) {
        int i = c / 10, l = c - 10 * i;
        float s = spv[w][c];
#pragma unroll
        for (int j = 0; j < 5; j++) s += sattn[i*5 + j] * spv[w][j*10 + l];
        float h = __half2float(__float2half(s));
        sva[w][c] = h;
        g_Va[row*64 + c] = __float2half(h);
    }
    for (int c = 50 + lane; c < 64; c += 32) g_Va[row*64 + c] = __float2half(0.f);
    __syncwarp();

    float s1 = 0.f, s2 = 0.f;
    for (int c = lane; c < 50; c += 32) {
        float vac = sva[w][c];
        s1 += vac * scs[c];
        s2 += 2.f * vac * (g_Rv[row*64 + c] + g_Rv[H + row*64 + c]);
        float tt = 0.f;
        for (int j2 = 0; j2 < 50; j2++) tt += sG[c*50 + j2] * sva[w][j2];
        s2 += vac * tt;
    }
#pragma unroll
    for (int o = 16; o > 0; o >>= 1) {
        s1 += __shfl_xor_sync(0xffffffffu, s1, o);
        s2 += __shfl_xor_sync(0xffffffffu, s2, o);
    }
    if (lane == 0) {
        g_part[row*2]     = g_rs[row]  + g_rs[NROWS + row]  + s1;
        g_part[row*2 + 1] = g_rss[row] + g_rss[NROWS + row] + s2;
    }
}

// ---- K2d: per-channel BN scale/shift ----
__global__ void k_stats(const float* __restrict__ gamma, const float* __restrict__ beta) {
    int c = threadIdx.x;
    float s1 = 0.f, s2 = 0.f;
    for (int b = 0; b < 32; b++) {
        long r = ((long)b * 256 + c) * 2;
        s1 += g_part[r]; s2 += g_part[r + 1];
    }
    const float invN = 1.0f / 131072.0f;
    float mean = s1 * invN;
    float var  = s2 * invN - mean * mean;
    float sc   = gamma[c] * rsqrtf(var + 1e-5f);
    g_sc[c] = sc;
    g_sh[c] = beta[c] - mean * sc;
}

// ---- K3: out = (vf + Va @ w_fc) * sc + sh ----
__global__ __launch_bounds__(256) void k_final(const float* __restrict__ v,
                                               float* __restrict__ out) {
    __shared__ __half As[128][72];
    __shared__ __half Bs[128][72];
    __shared__ float sSc[128], sSh[128];
    int rb = blockIdx.x * 128, cb = blockIdx.y * 128;
    int t = threadIdx.x, warp = t >> 5, lane = t & 31;
    int g = lane >> 2, tig = lane & 3;
    int warpM = warp >> 1, warpN = warp & 1;

    for (int i = t; i < 2048; i += 256) {
        int r = i >> 4, s = i & 15;
        *reinterpret_cast<uint2*>(&As[r][s*4]) =
            *reinterpret_cast<const uint2*>(&g_Va[(long)(rb + r)*64 + s*4]);
    }
    for (int i = t; i < 2048; i += 256) {
        int p = i >> 4, s = i & 15;
        *reinterpret_cast<uint2*>(&Bs[p][s*4]) =
            *reinterpret_cast<const uint2*>(&g_wfc[(long)(cb + p)*64 + s*4]);
    }
    if (t < 128) { int ch = (rb + t) & 255; sSc[t] = g_sc[ch]; sSh[t] = g_sh[ch]; }
    __syncthreads();

    float acc[2][8][4];
#pragma unroll
    for (int i = 0; i < 2; i++)
#pragma unroll
        for (int j = 0; j < 8; j++)
#pragma unroll
            for (int l = 0; l < 4; l++) acc[i][j][l] = 0.f;

#pragma unroll
    for (int ks = 0; ks < 64; ks += 16) {
        unsigned a[2][4];
#pragma unroll
        for (int mt = 0; mt < 2; mt++) {
            int r0 = warpM*32 + mt*16 + g;
            a[mt][0] = *reinterpret_cast<unsigned*>(&As[r0]  [ks+tig*2]);
            a[mt][1] = *reinterpret_cast<unsigned*>(&As[r0+8][ks+tig*2]);
            a[mt][2] = *reinterpret_cast<unsigned*>(&As[r0]  [ks+tig*2+8]);
            a[mt][3] = *reinterpret_cast<unsigned*>(&As[r0+8][ks+tig*2+8]);
        }
#pragma unroll
        for (int nt = 0; nt < 8; nt++) {
            int n0 = warpN*64 + nt*8 + g;
            unsigned b0 = *reinterpret_cast<unsigned*>(&Bs[n0][ks+tig*2]);
            unsigned b1 = *reinterpret_cast<unsigned*>(&Bs[n0][ks+tig*2+8]);
            mma16816(acc[0][nt], a[0], b0, b1);
            mma16816(acc[1][nt], a[1], b0, b1);
        }
    }

#pragma unroll
    for (int mt = 0; mt < 2; mt++) {
        int lr = warpM*32 + mt*16 + g;
        float sc0 = sSc[lr],   sh0 = sSh[lr];
        float sc1 = sSc[lr+8], sh1 = sSh[lr+8];
        long r0 = rb + lr;
#pragma unroll
        for (int nt = 0; nt < 8; nt++) {
            long col = cb + warpN*64 + nt*8 + tig*2;
            float2 v0 = *reinterpret_cast<const float2*>(v + r0*HW + col);
            float2 v1 = *reinterpret_cast<const float2*>(v + (r0+8)*HW + col);
            float2 o0, o1;
            o0.x = (v0.x + acc[mt][nt][0]) * sc0 + sh0;
            o0.y = (v0.y + acc[mt][nt][1]) * sc0 + sh0;
            o1.x = (v1.x + acc[mt][nt][2]) * sc1 + sh1;
            o1.y = (v1.y + acc[mt][nt][3]) * sc1 + sh1;
            *reinterpret_cast<float2*>(out + r0*HW + col)     = o0;
            *reinterpret_cast<float2*>(out + (r0+8)*HW + col) = o1;
        }
    }
}

extern "C" void kernel_launch(void* const* d_in, const int* in_sizes, int n_in,
                              void* d_out, int out_size) {
    const float* q     = (const float*)d_in[0];
    const float* k     = (const float*)d_in[1];
    const float* v     = (const float*)d_in[2];
    const float* wq    = (const float*)d_in[3];
    const float* wk    = (const float*)d_in[4];
    const float* wv    = (const float*)d_in[5];
    const float* wfc   = (const float*)d_in[6];
    const float* gamma = (const float*)d_in[7];
    const float* beta  = (const float*)d_in[8];
    float* out = (float*)d_out;

    static int smem_set = 0;
    if (!smem_set) {
        cudaFuncSetAttribute(k_proj, cudaFuncAttributeMaxDynamicSharedMemorySize, 81920);
        smem_set = 1;
    }

    k_prep<<<1024, 256>>>(wq, wk, wv, wfc);
    k_colsum<<<50, 128>>>(wfc);
    k_gram<<<2500, 128>>>(wfc);
    k_proj<<<384, 256, 81920>>>(q, k, v);       // profiled slot (launch index 3)
    k_logits<<<dim3(8, 32), 256>>>();
    k_softfin<<<32, 32>>>();
    k_mix<<<1024, 256>>>();
    k_stats<<<1, 256>>>(gamma, beta);
    k_final<<<dim3(64, 32), 256>>>(v, out);
}